// round 1
// baseline (speedup 1.0000x reference)
#include <cuda_runtime.h>
#include <cuda_bf16.h>

#define BATCH 4
#define SEQ   1024
#define DIN   1024
#define HD    64
#define NE    8
#define NHEAD 4
#define COUT  (HD*NE*NHEAD)   // 2048
#define MROWS (BATCH*SEQ)     // 4096
#define NBEH  (BATCH*NE*NHEAD) // 128

// Scratch (static device arrays — no allocations allowed)
__device__ float g_qp[(size_t)NBEH * HD * SEQ];        // [beh][d][s]  32 MB
__device__ float g_kp[(size_t)NBEH * HD * SEQ];        // [beh][d][s]  32 MB
__device__ float g_p [(size_t)1024 * 128 * 1024];      // [block][i][k] exp scores, 512 MB
__device__ float g_part[(size_t)1024 * SEQ];           // [block][k] partial outputs, 4 MB

// ---------------------------------------------------------------------------
// Projection GEMM: C = x @ W + b, written transposed to [beh][d][s]
// Tile 128x128, BK=16, 256 threads, 8x8 per thread.
// blockIdx.z: 0 -> Q (Wq,bq,g_qp), 1 -> K (Wk,bk,g_kp)
// ---------------------------------------------------------------------------
__global__ __launch_bounds__(256)
void proj_kernel(const float* __restrict__ x,
                 const float* __restrict__ Wq, const float* __restrict__ bq,
                 const float* __restrict__ Wk, const float* __restrict__ bk)
{
    const float* W    = blockIdx.z ? Wk : Wq;
    const float* bias = blockIdx.z ? bk : bq;
    float* outp       = blockIdx.z ? g_kp : g_qp;

    __shared__ float As[16 * 136];   // [kk][m], padded
    __shared__ float Bs[16 * 128];   // [kk][n]

    const int t  = threadIdx.x;
    const int ty = t >> 4;           // 0..15
    const int tx = t & 15;           // 0..15
    const int m0 = blockIdx.x * 128;
    const int n0 = blockIdx.y * 128;

    float acc[8][8];
#pragma unroll
    for (int i = 0; i < 8; i++)
#pragma unroll
        for (int j = 0; j < 8; j++) acc[i][j] = 0.f;

    for (int k0 = 0; k0 < DIN; k0 += 16) {
        __syncthreads();
        // A tile: x[m0..+128, k0..+16] -> As[kk][m]
#pragma unroll
        for (int j = 0; j < 2; j++) {
            int f   = t + j * 256;          // 0..511 float4 chunks
            int row = f >> 2;               // 0..127
            int kc  = f & 3;                // 0..3
            float4 v = *(const float4*)&x[(size_t)(m0 + row) * DIN + k0 + kc * 4];
            As[(kc * 4 + 0) * 136 + row] = v.x;
            As[(kc * 4 + 1) * 136 + row] = v.y;
            As[(kc * 4 + 2) * 136 + row] = v.z;
            As[(kc * 4 + 3) * 136 + row] = v.w;
        }
        // B tile: W[k0..+16, n0..+128] -> Bs[kk][n]
#pragma unroll
        for (int j = 0; j < 2; j++) {
            int f  = t + j * 256;
            int rk = f >> 5;                // 0..15
            int nc = f & 31;                // 0..31
            *(float4*)&Bs[rk * 128 + nc * 4] =
                *(const float4*)&W[(size_t)(k0 + rk) * COUT + n0 + nc * 4];
        }
        __syncthreads();

#pragma unroll
        for (int kk = 0; kk < 16; kk++) {
            float a[8], b[8];
            *(float4*)&a[0] = *(float4*)&As[kk * 136 + ty * 8];
            *(float4*)&a[4] = *(float4*)&As[kk * 136 + ty * 8 + 4];
            *(float4*)&b[0] = *(float4*)&Bs[kk * 128 + tx * 8];
            *(float4*)&b[4] = *(float4*)&Bs[kk * 128 + tx * 8 + 4];
#pragma unroll
            for (int i = 0; i < 8; i++)
#pragma unroll
                for (int j = 0; j < 8; j++)
                    acc[i][j] += a[i] * b[j];
        }
    }

    // Epilogue: scatter to [beh][d][s] layout; each column -> 2 float4 along s
    const int row0 = m0 + ty * 8;
    const int bb   = row0 >> 10;     // batch
    const int s0   = row0 & 1023;
#pragma unroll
    for (int j = 0; j < 8; j++) {
        int col = n0 + tx * 8 + j;
        int d   = col >> 5;          // hidden dim index
        int eh  = col & 31;          // e*4 + h
        float bv = bias[col];
        float* dst = outp + ((size_t)(bb * 32 + eh) * HD + d) * SEQ + s0;
        float4 v0 = { acc[0][j] + bv, acc[1][j] + bv, acc[2][j] + bv, acc[3][j] + bv };
        float4 v1 = { acc[4][j] + bv, acc[5][j] + bv, acc[6][j] + bv, acc[7][j] + bv };
        *(float4*)dst       = v0;
        *(float4*)(dst + 4) = v1;
    }
}

// ---------------------------------------------------------------------------
// Attention: block = (beh, 128-query tile).
// Pass 1: stream K tiles, compute s = (q.k)/8, write exp(s) to g_p, reduce Z per query.
// Pass 2: read g_p, scale by 1/Z, produce per-block partial out[k] (single writer).
// ---------------------------------------------------------------------------
#define ATTN_SMEM_FLOATS (8192 + 8192 + 128*17 + 128)

__global__ __launch_bounds__(256)
void attn_kernel()
{
    extern __shared__ float sm[];
    float* Qs   = sm;               // [64][128]
    float* Ks   = sm + 8192;        // [64][128]
    float* red  = sm + 16384;       // [128][17]
    float* Zbuf = red + 128 * 17;   // [128]

    const int t   = threadIdx.x;
    const int ty  = t >> 4;
    const int tx  = t & 15;
    const int bid = blockIdx.x;     // 0..1023
    const int beh = bid >> 3;
    const int it  = bid & 7;
    const int i0  = it * 128;

    const float* qb = g_qp + (size_t)beh * HD * SEQ;
    const float* kb = g_kp + (size_t)beh * HD * SEQ;
    float* pblk     = g_p  + (size_t)bid * 128 * 1024;

    // Load Q tile [64][128] (coalesced, conflict-free)
#pragma unroll
    for (int j = 0; j < 8; j++) {
        int f  = t + j * 256;       // 0..2047 float4 chunks
        int d  = f >> 5;
        int ic = (f & 31) * 4;
        *(float4*)&Qs[d * 128 + ic] = *(const float4*)&qb[(size_t)d * SEQ + i0 + ic];
    }
    if (t < 128) Zbuf[t] = 0.f;
    __syncthreads();

    const float SCALE = 0.125f;     // 1/sqrt(64)

    // -------- Pass 1 --------
    for (int kt = 0; kt < 8; kt++) {
#pragma unroll
        for (int j = 0; j < 8; j++) {
            int f  = t + j * 256;
            int d  = f >> 5;
            int kc = (f & 31) * 4;
            *(float4*)&Ks[d * 128 + kc] = *(const float4*)&kb[(size_t)d * SEQ + kt * 128 + kc];
        }
        __syncthreads();

        float acc[8][8];
#pragma unroll
        for (int i = 0; i < 8; i++)
#pragma unroll
            for (int j = 0; j < 8; j++) acc[i][j] = 0.f;

#pragma unroll 8
        for (int d = 0; d < 64; d++) {
            float a[8], b[8];
            *(float4*)&a[0] = *(float4*)&Qs[d * 128 + ty * 8];
            *(float4*)&a[4] = *(float4*)&Qs[d * 128 + ty * 8 + 4];
            *(float4*)&b[0] = *(float4*)&Ks[d * 128 + tx * 8];
            *(float4*)&b[4] = *(float4*)&Ks[d * 128 + tx * 8 + 4];
#pragma unroll
            for (int i = 0; i < 8; i++)
#pragma unroll
                for (int j = 0; j < 8; j++)
                    acc[i][j] += a[i] * b[j];
        }

        // exp + store P + row partial sums
#pragma unroll
        for (int i = 0; i < 8; i++) {
            float p[8];
            float rp = 0.f;
#pragma unroll
            for (int j = 0; j < 8; j++) {
                p[j] = __expf(acc[i][j] * SCALE);
                rp += p[j];
            }
            int irow = ty * 8 + i;
            float* dst = pblk + (size_t)irow * 1024 + kt * 128 + tx * 8;
            *(float4*)dst       = *(float4*)&p[0];
            *(float4*)(dst + 4) = *(float4*)&p[4];
            red[irow * 17 + tx] = rp;
        }
        __syncthreads();

        if (t < 128) {
            float z = 0.f;
#pragma unroll
            for (int r = 0; r < 16; r++) z += red[t * 17 + r];
            Zbuf[t] += z;
        }
        __syncthreads();
    }

    if (t < 128) Zbuf[t] = 1.f / Zbuf[t];
    __syncthreads();

    // -------- Pass 2: out[k] = sum_i P[i][k] * rZ[i] (each thread owns 4 k's)
    float s0 = 0.f, s1 = 0.f, s2 = 0.f, s3 = 0.f;
#pragma unroll 8
    for (int i = 0; i < 128; i++) {
        float r = Zbuf[i];
        const float* row = pblk + (size_t)i * 1024;
        s0 += row[t      ] * r;
        s1 += row[t + 256] * r;
        s2 += row[t + 512] * r;
        s3 += row[t + 768] * r;
    }
    float* gp = g_part + (size_t)bid * 1024;
    gp[t      ] = s0;
    gp[t + 256] = s1;
    gp[t + 512] = s2;
    gp[t + 768] = s3;
}

// ---------------------------------------------------------------------------
// Final reduce: out[b][k][e] = sum over h(4), it(8) of g_part
// ---------------------------------------------------------------------------
__global__ __launch_bounds__(256)
void reduce_kernel(float* __restrict__ out)
{
    int tid = blockIdx.x * blockDim.x + threadIdx.x;
    if (tid >= BATCH * SEQ * NE) return;
    int e    = tid & 7;
    int kpos = (tid >> 3) & 1023;
    int b    = tid >> 13;
    float s = 0.f;
#pragma unroll
    for (int h = 0; h < NHEAD; h++) {
        int beh = b * 32 + e * 4 + h;
#pragma unroll
        for (int itq = 0; itq < 8; itq++)
            s += g_part[(size_t)(beh * 8 + itq) * 1024 + kpos];
    }
    out[tid] = s;
}

// ---------------------------------------------------------------------------
extern "C" void kernel_launch(void* const* d_in, const int* in_sizes, int n_in,
                              void* d_out, int out_size)
{
    const float* x  = (const float*)d_in[0];
    const float* Wq = (const float*)d_in[1];
    const float* bq = (const float*)d_in[2];
    const float* Wk = (const float*)d_in[3];
    const float* bk = (const float*)d_in[4];
    float* out = (float*)d_out;

    dim3 gproj(MROWS / 128, COUT / 128, 2);
    proj_kernel<<<gproj, 256>>>(x, Wq, bq, Wk, bk);

    int smem = ATTN_SMEM_FLOATS * (int)sizeof(float);
    cudaFuncSetAttribute(attn_kernel, cudaFuncAttributeMaxDynamicSharedMemorySize, smem);
    attn_kernel<<<1024, 256, smem>>>();

    reduce_kernel<<<(BATCH * SEQ * NE + 255) / 256, 256>>>(out);
}

// round 3
// speedup vs baseline: 1.6915x; 1.6915x over previous
#include <cuda_runtime.h>
#include <cuda_bf16.h>
#include <cstdint>

#define BATCH 4
#define SEQ   1024
#define DIN   1024
#define HD    64
#define NE    8
#define NHEAD 4
#define COUT  (HD*NE*NHEAD)    // 2048
#define MROWS (BATCH*SEQ)      // 4096
#define NBEH  (BATCH*NE*NHEAD) // 128

// ---------------------------------------------------------------------------
// Scratch (no allocations allowed)
// ---------------------------------------------------------------------------
__device__ float g_qp[(size_t)NBEH * HD * SEQ];        // [beh][d][s]  32 MB
__device__ float g_kp[(size_t)NBEH * HD * SEQ];        // [beh][d][s]  32 MB
__device__ float g_p [(size_t)1024 * 128 * 1024];      // exp scores, 512 MB
__device__ float g_part[(size_t)1024 * SEQ];           // partial outputs, 4 MB

__device__ __nv_bfloat16 g_xh[(size_t)MROWS * DIN];    // x hi, 8 MB
__device__ __nv_bfloat16 g_xl[(size_t)MROWS * DIN];    // x lo, 8 MB
__device__ __nv_bfloat16 g_wth[2][(size_t)COUT * DIN]; // W^T hi (q,k)
__device__ __nv_bfloat16 g_wtl[2][(size_t)COUT * DIN]; // W^T lo (q,k)

// ---------------------------------------------------------------------------
// sm_80+ primitives (legal under compute_100 target)
// ---------------------------------------------------------------------------
__device__ __forceinline__ uint32_t smem_u32(const void* p) {
    uint32_t a;
    asm("{ .reg .u64 t; cvta.to.shared.u64 t, %1; cvt.u32.u64 %0, t; }" : "=r"(a) : "l"(p));
    return a;
}
__device__ __forceinline__ void ldm_x4(uint32_t* r, uint32_t addr) {
    asm volatile("ldmatrix.sync.aligned.m8n8.x4.shared.b16 {%0,%1,%2,%3}, [%4];"
        : "=r"(r[0]), "=r"(r[1]), "=r"(r[2]), "=r"(r[3]) : "r"(addr));
}
__device__ __forceinline__ void mma_bf16(float* d, const uint32_t* a, const uint32_t* b) {
    asm volatile("mma.sync.aligned.m16n8k16.row.col.f32.bf16.bf16.f32 "
        "{%0,%1,%2,%3}, {%4,%5,%6,%7}, {%8,%9}, {%0,%1,%2,%3};"
        : "+f"(d[0]), "+f"(d[1]), "+f"(d[2]), "+f"(d[3])
        : "r"(a[0]), "r"(a[1]), "r"(a[2]), "r"(a[3]), "r"(b[0]), "r"(b[1]));
}
__device__ __forceinline__ void cp16(uint32_t dst, const void* src) {
    asm volatile("cp.async.cg.shared.global [%0], [%1], 16;" :: "r"(dst), "l"(src));
}
#define CP_COMMIT() asm volatile("cp.async.commit_group;" ::: "memory")
#define CP_WAIT1()  asm volatile("cp.async.wait_group 1;" ::: "memory")
#define CP_WAIT0()  asm volatile("cp.async.wait_group 0;" ::: "memory")

// ---------------------------------------------------------------------------
// Split-convert x: hi = bf16(v), lo = bf16(v - hi)
// ---------------------------------------------------------------------------
__global__ __launch_bounds__(256)
void convert_x_kernel(const float* __restrict__ x)
{
    int i = blockIdx.x * 256 + threadIdx.x;      // float4 index, total 1M
    float4 v = ((const float4*)x)[i];
    __nv_bfloat16 hx = __float2bfloat16(v.x), hy = __float2bfloat16(v.y);
    __nv_bfloat16 hz = __float2bfloat16(v.z), hw = __float2bfloat16(v.w);
    __nv_bfloat162* ph = (__nv_bfloat162*)g_xh;
    __nv_bfloat162* pl = (__nv_bfloat162*)g_xl;
    ph[i * 2 + 0] = __nv_bfloat162(hx, hy);
    ph[i * 2 + 1] = __nv_bfloat162(hz, hw);
    pl[i * 2 + 0] = __nv_bfloat162(__float2bfloat16(v.x - __bfloat162float(hx)),
                                   __float2bfloat16(v.y - __bfloat162float(hy)));
    pl[i * 2 + 1] = __nv_bfloat162(__float2bfloat16(v.z - __bfloat162float(hz)),
                                   __float2bfloat16(v.w - __bfloat162float(hw)));
}

// ---------------------------------------------------------------------------
// Split-convert + transpose W: Wt[n][k] = W[k][n]  (hi/lo)
// ---------------------------------------------------------------------------
__global__ __launch_bounds__(256)
void convert_wt_kernel(const float* __restrict__ Wq, const float* __restrict__ Wk)
{
    __shared__ float sm[32][33];
    const float* W = blockIdx.z ? Wk : Wq;
    __nv_bfloat16* oh = g_wth[blockIdx.z];
    __nv_bfloat16* ol = g_wtl[blockIdx.z];
    int n0 = blockIdx.x * 32, k0 = blockIdx.y * 32;
    int tx = threadIdx.x & 31, ty = threadIdx.x >> 5;   // 32 x 8
#pragma unroll
    for (int j = 0; j < 4; j++)
        sm[ty + j * 8][tx] = W[(size_t)(k0 + ty + j * 8) * COUT + n0 + tx];
    __syncthreads();
#pragma unroll
    for (int j = 0; j < 4; j++) {
        int row = ty + j * 8;                            // local n
        float v = sm[tx][row];
        __nv_bfloat16 h = __float2bfloat16(v);
        size_t o = (size_t)(n0 + row) * DIN + k0 + tx;
        oh[o] = h;
        ol[o] = __float2bfloat16(v - __bfloat162float(h));
    }
}

// ---------------------------------------------------------------------------
// mma.sync projection GEMM: C = x@W + b via xh@Wh + xh@Wl + xl@Wh
// 128x128 block tile, BK=32, 8 warps (warp tile 32x64), cp.async double buffer.
// Epilogue adds bias and writes transposed [beh][d][s].
// ---------------------------------------------------------------------------
#define SROWB   80                 // smem row stride bytes (40 bf16) - conflict-free
#define TILE_B  (128 * SROWB)      // 10240 B per operand tile
#define STAGE_B (4 * TILE_B)       // Ah, Al, Bh, Bl
#define PROJ_SMEM (2 * STAGE_B)    // 81920 B

__device__ __forceinline__ void proj_prefetch(
    uint32_t sb, int stage, int k0, int t,
    const __nv_bfloat16* a_h, const __nv_bfloat16* a_l,
    const __nv_bfloat16* b_h, const __nv_bfloat16* b_l)
{
    const __nv_bfloat16* srcs[4] = { a_h, a_l, b_h, b_l };
    uint32_t st = sb + stage * STAGE_B;
#pragma unroll
    for (int tile = 0; tile < 4; tile++) {
#pragma unroll
        for (int j = 0; j < 2; j++) {
            int idx = t + j * 256;               // 0..511
            int row = idx >> 2, cc = idx & 3;
            cp16(st + tile * TILE_B + row * SROWB + cc * 16,
                 srcs[tile] + (size_t)row * DIN + k0 + cc * 8);
        }
    }
    CP_COMMIT();
}

__global__ __launch_bounds__(256)
void proj_mma_kernel(const float* __restrict__ bq, const float* __restrict__ bk)
{
    extern __shared__ char smc[];
    const uint32_t sb = smem_u32(smc);
    const int t = threadIdx.x, wid = t >> 5, lane = t & 31;
    const int m0 = blockIdx.x * 128, n0 = blockIdx.y * 128, z = blockIdx.z;
    const int wm = (wid & 3) * 32, wn = (wid >> 2) * 64;

    const __nv_bfloat16* a_h = g_xh + (size_t)m0 * DIN;
    const __nv_bfloat16* a_l = g_xl + (size_t)m0 * DIN;
    const __nv_bfloat16* b_h = g_wth[z] + (size_t)n0 * DIN;
    const __nv_bfloat16* b_l = g_wtl[z] + (size_t)n0 * DIN;
    const float* bias = z ? bk : bq;
    float* outp = z ? g_kp : g_qp;

    float acc[2][8][4];
#pragma unroll
    for (int mi = 0; mi < 2; mi++)
#pragma unroll
        for (int ni = 0; ni < 8; ni++)
#pragma unroll
            for (int r = 0; r < 4; r++) acc[mi][ni][r] = 0.f;

    proj_prefetch(sb, 0, 0, t, a_h, a_l, b_h, b_l);

    const int NCHUNK = DIN / 32;
    for (int c = 0; c < NCHUNK; ++c) {
        if (c + 1 < NCHUNK) {
            proj_prefetch(sb, (c + 1) & 1, (c + 1) * 32, t, a_h, a_l, b_h, b_l);
            CP_WAIT1();
        } else {
            CP_WAIT0();
        }
        __syncthreads();

        const uint32_t st  = sb + (c & 1) * STAGE_B;
        const uint32_t sAh = st, sAl = st + TILE_B;
        const uint32_t sBh = st + 2 * TILE_B, sBl = st + 3 * TILE_B;

#pragma unroll
        for (int kk = 0; kk < 32; kk += 16) {
            uint32_t ah[2][4], al[2][4], bh[4][4], bl[4][4];
            const int arow = wm + (lane & 15);
            const int acol = kk + (lane >> 4) * 8;
#pragma unroll
            for (int mi = 0; mi < 2; mi++) {
                ldm_x4(ah[mi], sAh + (arow + mi * 16) * SROWB + acol * 2);
                ldm_x4(al[mi], sAl + (arow + mi * 16) * SROWB + acol * 2);
            }
            const int g = lane >> 3;
            const int brow_off = (g >> 1) * 8 + (lane & 7);
            const int bcol = kk + (g & 1) * 8;
#pragma unroll
            for (int np = 0; np < 4; np++) {
                int brow = wn + np * 16 + brow_off;
                ldm_x4(bh[np], sBh + brow * SROWB + bcol * 2);
                ldm_x4(bl[np], sBl + brow * SROWB + bcol * 2);
            }
#pragma unroll
            for (int mi = 0; mi < 2; mi++)
#pragma unroll
                for (int ni = 0; ni < 8; ni++) {
                    const uint32_t* Bh = &bh[ni >> 1][(ni & 1) * 2];
                    const uint32_t* Bl = &bl[ni >> 1][(ni & 1) * 2];
                    mma_bf16(acc[mi][ni], ah[mi], Bh);
                    mma_bf16(acc[mi][ni], ah[mi], Bl);
                    mma_bf16(acc[mi][ni], al[mi], Bh);
                }
        }
        __syncthreads();
    }

    // Epilogue: bias + transposed [beh][d][s] store (32B-sector friendly)
#pragma unroll
    for (int mi = 0; mi < 2; mi++) {
        int r = wm + mi * 16 + (lane >> 2);
        int m = m0 + r;
        int b = m >> 10, s = m & 1023;
#pragma unroll
        for (int ni = 0; ni < 8; ni++) {
            int col = n0 + wn + ni * 8 + (lane & 3) * 2;
            float bv0 = __ldg(&bias[col]);
            float bv1 = __ldg(&bias[col + 1]);
            int d = col >> 5, e0 = col & 31;            // col even -> col+1 same d
            float* base0 = outp + ((size_t)(b * 32 + e0) * HD + d) * SEQ;
            float* base1 = outp + ((size_t)(b * 32 + e0 + 1) * HD + d) * SEQ;
            base0[s]     = acc[mi][ni][0] + bv0;
            base1[s]     = acc[mi][ni][1] + bv1;
            base0[s + 8] = acc[mi][ni][2] + bv0;
            base1[s + 8] = acc[mi][ni][3] + bv1;
        }
    }
}

// ---------------------------------------------------------------------------
// Attention (unchanged): block = (beh, 128-query tile).
// ---------------------------------------------------------------------------
#define ATTN_SMEM_FLOATS (8192 + 8192 + 128*17 + 128)

__global__ __launch_bounds__(256)
void attn_kernel()
{
    extern __shared__ float sm[];
    float* Qs   = sm;
    float* Ks   = sm + 8192;
    float* red  = sm + 16384;
    float* Zbuf = red + 128 * 17;

    const int t   = threadIdx.x;
    const int ty  = t >> 4;
    const int tx  = t & 15;
    const int bid = blockIdx.x;
    const int beh = bid >> 3;
    const int it  = bid & 7;
    const int i0  = it * 128;

    const float* qb = g_qp + (size_t)beh * HD * SEQ;
    const float* kb = g_kp + (size_t)beh * HD * SEQ;
    float* pblk     = g_p  + (size_t)bid * 128 * 1024;

#pragma unroll
    for (int j = 0; j < 8; j++) {
        int f  = t + j * 256;
        int d  = f >> 5;
        int ic = (f & 31) * 4;
        *(float4*)&Qs[d * 128 + ic] = *(const float4*)&qb[(size_t)d * SEQ + i0 + ic];
    }
    if (t < 128) Zbuf[t] = 0.f;
    __syncthreads();

    const float SCALE = 0.125f;

    for (int kt = 0; kt < 8; kt++) {
#pragma unroll
        for (int j = 0; j < 8; j++) {
            int f  = t + j * 256;
            int d  = f >> 5;
            int kc = (f & 31) * 4;
            *(float4*)&Ks[d * 128 + kc] = *(const float4*)&kb[(size_t)d * SEQ + kt * 128 + kc];
        }
        __syncthreads();

        float acc[8][8];
#pragma unroll
        for (int i = 0; i < 8; i++)
#pragma unroll
            for (int j = 0; j < 8; j++) acc[i][j] = 0.f;

#pragma unroll 8
        for (int d = 0; d < 64; d++) {
            float a[8], b[8];
            *(float4*)&a[0] = *(float4*)&Qs[d * 128 + ty * 8];
            *(float4*)&a[4] = *(float4*)&Qs[d * 128 + ty * 8 + 4];
            *(float4*)&b[0] = *(float4*)&Ks[d * 128 + tx * 8];
            *(float4*)&b[4] = *(float4*)&Ks[d * 128 + tx * 8 + 4];
#pragma unroll
            for (int i = 0; i < 8; i++)
#pragma unroll
                for (int j = 0; j < 8; j++)
                    acc[i][j] += a[i] * b[j];
        }

#pragma unroll
        for (int i = 0; i < 8; i++) {
            float p[8];
            float rp = 0.f;
#pragma unroll
            for (int j = 0; j < 8; j++) {
                p[j] = __expf(acc[i][j] * SCALE);
                rp += p[j];
            }
            int irow = ty * 8 + i;
            float* dst = pblk + (size_t)irow * 1024 + kt * 128 + tx * 8;
            *(float4*)dst       = *(float4*)&p[0];
            *(float4*)(dst + 4) = *(float4*)&p[4];
            red[irow * 17 + tx] = rp;
        }
        __syncthreads();

        if (t < 128) {
            float z = 0.f;
#pragma unroll
            for (int r = 0; r < 16; r++) z += red[t * 17 + r];
            Zbuf[t] += z;
        }
        __syncthreads();
    }

    if (t < 128) Zbuf[t] = 1.f / Zbuf[t];
    __syncthreads();

    float s0 = 0.f, s1 = 0.f, s2 = 0.f, s3 = 0.f;
#pragma unroll 8
    for (int i = 0; i < 128; i++) {
        float r = Zbuf[i];
        const float* row = pblk + (size_t)i * 1024;
        s0 += row[t      ] * r;
        s1 += row[t + 256] * r;
        s2 += row[t + 512] * r;
        s3 += row[t + 768] * r;
    }
    float* gp = g_part + (size_t)bid * 1024;
    gp[t      ] = s0;
    gp[t + 256] = s1;
    gp[t + 512] = s2;
    gp[t + 768] = s3;
}

// ---------------------------------------------------------------------------
// Final reduce (unchanged)
// ---------------------------------------------------------------------------
__global__ __launch_bounds__(256)
void reduce_kernel(float* __restrict__ out)
{
    int tid = blockIdx.x * blockDim.x + threadIdx.x;
    if (tid >= BATCH * SEQ * NE) return;
    int e    = tid & 7;
    int kpos = (tid >> 3) & 1023;
    int b    = tid >> 13;
    float s = 0.f;
#pragma unroll
    for (int h = 0; h < NHEAD; h++) {
        int beh = b * 32 + e * 4 + h;
#pragma unroll
        for (int itq = 0; itq < 8; itq++)
            s += g_part[(size_t)(beh * 8 + itq) * 1024 + kpos];
    }
    out[tid] = s;
}

// ---------------------------------------------------------------------------
extern "C" void kernel_launch(void* const* d_in, const int* in_sizes, int n_in,
                              void* d_out, int out_size)
{
    const float* x  = (const float*)d_in[0];
    const float* Wq = (const float*)d_in[1];
    const float* bq = (const float*)d_in[2];
    const float* Wk = (const float*)d_in[3];
    const float* bk = (const float*)d_in[4];
    float* out = (float*)d_out;

    convert_x_kernel<<<(MROWS * DIN / 4) / 256, 256>>>(x);
    convert_wt_kernel<<<dim3(COUT / 32, DIN / 32, 2), 256>>>(Wq, Wk);

    cudaFuncSetAttribute(proj_mma_kernel, cudaFuncAttributeMaxDynamicSharedMemorySize, PROJ_SMEM);
    proj_mma_kernel<<<dim3(MROWS / 128, COUT / 128, 2), 256, PROJ_SMEM>>>(bq, bk);

    int smem = ATTN_SMEM_FLOATS * (int)sizeof(float);
    cudaFuncSetAttribute(attn_kernel, cudaFuncAttributeMaxDynamicSharedMemorySize, smem);
    attn_kernel<<<1024, 256, smem>>>();

    reduce_kernel<<<(BATCH * SEQ * NE + 255) / 256, 256>>>(out);
}

// round 4
// speedup vs baseline: 2.3854x; 1.4102x over previous
#include <cuda_runtime.h>
#include <cuda_bf16.h>
#include <cstdint>

#define BATCH 4
#define SEQ   1024
#define DIN   1024
#define HD    64
#define NE    8
#define NHEAD 4
#define COUT  (HD*NE*NHEAD)    // 2048
#define MROWS (BATCH*SEQ)      // 4096
#define NBEH  (BATCH*NE*NHEAD) // 128

// ---------------------------------------------------------------------------
// Scratch (no allocations allowed)
// ---------------------------------------------------------------------------
__device__ float g_part[(size_t)2048 * SEQ];            // per-block partials, 8 MB

__device__ __nv_bfloat16 g_xh[(size_t)MROWS * DIN];     // x hi
__device__ __nv_bfloat16 g_xl[(size_t)MROWS * DIN];     // x lo
__device__ __nv_bfloat16 g_wth[2][(size_t)COUT * DIN];  // W^T hi (q,k)
__device__ __nv_bfloat16 g_wtl[2][(size_t)COUT * DIN];  // W^T lo (q,k)

// q/k split bf16, layout [beh][d][s]
__device__ __nv_bfloat16 g_qh[(size_t)NBEH * HD * SEQ];
__device__ __nv_bfloat16 g_ql[(size_t)NBEH * HD * SEQ];
__device__ __nv_bfloat16 g_kh[(size_t)NBEH * HD * SEQ];
__device__ __nv_bfloat16 g_kl[(size_t)NBEH * HD * SEQ];

// ---------------------------------------------------------------------------
// sm_80+ primitives
// ---------------------------------------------------------------------------
__device__ __forceinline__ uint32_t smem_u32(const void* p) {
    uint32_t a;
    asm("{ .reg .u64 t; cvta.to.shared.u64 t, %1; cvt.u32.u64 %0, t; }" : "=r"(a) : "l"(p));
    return a;
}
__device__ __forceinline__ void ldm_x4(uint32_t* r, uint32_t addr) {
    asm volatile("ldmatrix.sync.aligned.m8n8.x4.shared.b16 {%0,%1,%2,%3}, [%4];"
        : "=r"(r[0]), "=r"(r[1]), "=r"(r[2]), "=r"(r[3]) : "r"(addr));
}
__device__ __forceinline__ void ldm_x4t(uint32_t* r, uint32_t addr) {
    asm volatile("ldmatrix.sync.aligned.m8n8.x4.trans.shared.b16 {%0,%1,%2,%3}, [%4];"
        : "=r"(r[0]), "=r"(r[1]), "=r"(r[2]), "=r"(r[3]) : "r"(addr));
}
__device__ __forceinline__ void mma_bf16(float* d, const uint32_t* a, const uint32_t* b) {
    asm volatile("mma.sync.aligned.m16n8k16.row.col.f32.bf16.bf16.f32 "
        "{%0,%1,%2,%3}, {%4,%5,%6,%7}, {%8,%9}, {%0,%1,%2,%3};"
        : "+f"(d[0]), "+f"(d[1]), "+f"(d[2]), "+f"(d[3])
        : "r"(a[0]), "r"(a[1]), "r"(a[2]), "r"(a[3]), "r"(b[0]), "r"(b[1]));
}
__device__ __forceinline__ void cp16(uint32_t dst, const void* src) {
    asm volatile("cp.async.cg.shared.global [%0], [%1], 16;" :: "r"(dst), "l"(src));
}
#define CP_COMMIT() asm volatile("cp.async.commit_group;" ::: "memory")
#define CP_WAIT1()  asm volatile("cp.async.wait_group 1;" ::: "memory")
#define CP_WAIT0()  asm volatile("cp.async.wait_group 0;" ::: "memory")

// ---------------------------------------------------------------------------
// Split-convert x
// ---------------------------------------------------------------------------
__global__ __launch_bounds__(256)
void convert_x_kernel(const float* __restrict__ x)
{
    int i = blockIdx.x * 256 + threadIdx.x;
    float4 v = ((const float4*)x)[i];
    __nv_bfloat16 hx = __float2bfloat16(v.x), hy = __float2bfloat16(v.y);
    __nv_bfloat16 hz = __float2bfloat16(v.z), hw = __float2bfloat16(v.w);
    __nv_bfloat162* ph = (__nv_bfloat162*)g_xh;
    __nv_bfloat162* pl = (__nv_bfloat162*)g_xl;
    ph[i * 2 + 0] = __nv_bfloat162(hx, hy);
    ph[i * 2 + 1] = __nv_bfloat162(hz, hw);
    pl[i * 2 + 0] = __nv_bfloat162(__float2bfloat16(v.x - __bfloat162float(hx)),
                                   __float2bfloat16(v.y - __bfloat162float(hy)));
    pl[i * 2 + 1] = __nv_bfloat162(__float2bfloat16(v.z - __bfloat162float(hz)),
                                   __float2bfloat16(v.w - __bfloat162float(hw)));
}

// ---------------------------------------------------------------------------
// Split-convert + transpose W
// ---------------------------------------------------------------------------
__global__ __launch_bounds__(256)
void convert_wt_kernel(const float* __restrict__ Wq, const float* __restrict__ Wk)
{
    __shared__ float sm[32][33];
    const float* W = blockIdx.z ? Wk : Wq;
    __nv_bfloat16* oh = g_wth[blockIdx.z];
    __nv_bfloat16* ol = g_wtl[blockIdx.z];
    int n0 = blockIdx.x * 32, k0 = blockIdx.y * 32;
    int tx = threadIdx.x & 31, ty = threadIdx.x >> 5;
#pragma unroll
    for (int j = 0; j < 4; j++)
        sm[ty + j * 8][tx] = W[(size_t)(k0 + ty + j * 8) * COUT + n0 + tx];
    __syncthreads();
#pragma unroll
    for (int j = 0; j < 4; j++) {
        int row = ty + j * 8;
        float v = sm[tx][row];
        __nv_bfloat16 h = __float2bfloat16(v);
        size_t o = (size_t)(n0 + row) * DIN + k0 + tx;
        oh[o] = h;
        ol[o] = __float2bfloat16(v - __bfloat162float(h));
    }
}

// ---------------------------------------------------------------------------
// mma.sync projection GEMM; epilogue emits split bf16 q/k in [beh][d][s]
// ---------------------------------------------------------------------------
#define SROWB   80
#define TILE_B  (128 * SROWB)
#define STAGE_B (4 * TILE_B)
#define PROJ_SMEM (2 * STAGE_B)

__device__ __forceinline__ void split_store(__nv_bfloat16* ph, __nv_bfloat16* pl,
                                            size_t o, float v)
{
    __nv_bfloat16 h = __float2bfloat16(v);
    ph[o] = h;
    pl[o] = __float2bfloat16(v - __bfloat162float(h));
}

__device__ __forceinline__ void proj_prefetch(
    uint32_t sb, int stage, int k0, int t,
    const __nv_bfloat16* a_h, const __nv_bfloat16* a_l,
    const __nv_bfloat16* b_h, const __nv_bfloat16* b_l)
{
    const __nv_bfloat16* srcs[4] = { a_h, a_l, b_h, b_l };
    uint32_t st = sb + stage * STAGE_B;
#pragma unroll
    for (int tile = 0; tile < 4; tile++) {
#pragma unroll
        for (int j = 0; j < 2; j++) {
            int idx = t + j * 256;
            int row = idx >> 2, cc = idx & 3;
            cp16(st + tile * TILE_B + row * SROWB + cc * 16,
                 srcs[tile] + (size_t)row * DIN + k0 + cc * 8);
        }
    }
    CP_COMMIT();
}

__global__ __launch_bounds__(256)
void proj_mma_kernel(const float* __restrict__ bq, const float* __restrict__ bk)
{
    extern __shared__ char smc[];
    const uint32_t sb = smem_u32(smc);
    const int t = threadIdx.x, wid = t >> 5, lane = t & 31;
    const int m0 = blockIdx.x * 128, n0 = blockIdx.y * 128, z = blockIdx.z;
    const int wm = (wid & 3) * 32, wn = (wid >> 2) * 64;

    const __nv_bfloat16* a_h = g_xh + (size_t)m0 * DIN;
    const __nv_bfloat16* a_l = g_xl + (size_t)m0 * DIN;
    const __nv_bfloat16* b_h = g_wth[z] + (size_t)n0 * DIN;
    const __nv_bfloat16* b_l = g_wtl[z] + (size_t)n0 * DIN;
    const float* bias = z ? bk : bq;
    __nv_bfloat16* oh = z ? g_kh : g_qh;
    __nv_bfloat16* ol = z ? g_kl : g_ql;

    float acc[2][8][4];
#pragma unroll
    for (int mi = 0; mi < 2; mi++)
#pragma unroll
        for (int ni = 0; ni < 8; ni++)
#pragma unroll
            for (int r = 0; r < 4; r++) acc[mi][ni][r] = 0.f;

    proj_prefetch(sb, 0, 0, t, a_h, a_l, b_h, b_l);

    const int NCHUNK = DIN / 32;
    for (int c = 0; c < NCHUNK; ++c) {
        if (c + 1 < NCHUNK) {
            proj_prefetch(sb, (c + 1) & 1, (c + 1) * 32, t, a_h, a_l, b_h, b_l);
            CP_WAIT1();
        } else {
            CP_WAIT0();
        }
        __syncthreads();

        const uint32_t st  = sb + (c & 1) * STAGE_B;
        const uint32_t sAh = st, sAl = st + TILE_B;
        const uint32_t sBh = st + 2 * TILE_B, sBl = st + 3 * TILE_B;

#pragma unroll
        for (int kk = 0; kk < 32; kk += 16) {
            uint32_t ah[2][4], al[2][4], bh[4][4], bl[4][4];
            const int arow = wm + (lane & 15);
            const int acol = kk + (lane >> 4) * 8;
#pragma unroll
            for (int mi = 0; mi < 2; mi++) {
                ldm_x4(ah[mi], sAh + (arow + mi * 16) * SROWB + acol * 2);
                ldm_x4(al[mi], sAl + (arow + mi * 16) * SROWB + acol * 2);
            }
            const int g = lane >> 3;
            const int brow_off = (g >> 1) * 8 + (lane & 7);
            const int bcol = kk + (g & 1) * 8;
#pragma unroll
            for (int np = 0; np < 4; np++) {
                int brow = wn + np * 16 + brow_off;
                ldm_x4(bh[np], sBh + brow * SROWB + bcol * 2);
                ldm_x4(bl[np], sBl + brow * SROWB + bcol * 2);
            }
#pragma unroll
            for (int mi = 0; mi < 2; mi++)
#pragma unroll
                for (int ni = 0; ni < 8; ni++) {
                    const uint32_t* Bh = &bh[ni >> 1][(ni & 1) * 2];
                    const uint32_t* Bl = &bl[ni >> 1][(ni & 1) * 2];
                    mma_bf16(acc[mi][ni], ah[mi], Bh);
                    mma_bf16(acc[mi][ni], ah[mi], Bl);
                    mma_bf16(acc[mi][ni], al[mi], Bh);
                }
        }
        __syncthreads();
    }

    // Epilogue: bias + split-bf16 store to [beh][d][s]
#pragma unroll
    for (int mi = 0; mi < 2; mi++) {
        int r = wm + mi * 16 + (lane >> 2);
        int m = m0 + r;
        int b = m >> 10, s = m & 1023;
#pragma unroll
        for (int ni = 0; ni < 8; ni++) {
            int col = n0 + wn + ni * 8 + (lane & 3) * 2;
            float bv0 = __ldg(&bias[col]);
            float bv1 = __ldg(&bias[col + 1]);
            int d = col >> 5, e0 = col & 31;
            size_t o0 = ((size_t)(b * 32 + e0) * HD + d) * SEQ + s;
            size_t o1 = ((size_t)(b * 32 + e0 + 1) * HD + d) * SEQ + s;
            split_store(oh, ol, o0,     acc[mi][ni][0] + bv0);
            split_store(oh, ol, o1,     acc[mi][ni][1] + bv1);
            split_store(oh, ol, o0 + 8, acc[mi][ni][2] + bv0);
            split_store(oh, ol, o1 + 8, acc[mi][ni][3] + bv1);
        }
    }
}

// ---------------------------------------------------------------------------
// MMA attention: block = (beh, 64-query tile). 8 warps (2q x 4k).
// Scores via split-bf16 mma.sync (trans ldmatrix on [d][s] tiles),
// exp -> smem P (bf16), Z in regs, pass-2 smem column sums.
// ---------------------------------------------------------------------------
#define AQ_STRIDE 144                 // Q tile row stride (64 q * 2B + pad)
#define AK_STRIDE 528                 // K tile row stride (256 k * 2B + pad)
#define AP_STRIDE 2064                // P row stride (1024 k * 2B + pad)
#define SQH 0
#define SQL (SQH + 64 * AQ_STRIDE)    // 9216
#define SKH (SQL + 64 * AQ_STRIDE)    // 18432
#define SKL (SKH + 64 * AK_STRIDE)    // 52224
#define SP  (SKL + 64 * AK_STRIDE)    // 86016
#define SRED (SP + 64 * AP_STRIDE)    // 218112
#define SRZ  (SRED + 64 * 4 * 4)      // 219136
#define ATTN_SMEM (SRZ + 64 * 4)      // 219392

__global__ __launch_bounds__(256)
void attn_mma_kernel()
{
    extern __shared__ char smc[];
    const uint32_t sb = smem_u32(smc);
    const int t = threadIdx.x, wid = t >> 5, lane = t & 31;
    const int wq = wid >> 2, wk = wid & 3;
    const int bid = blockIdx.x, beh = bid >> 4, qt = bid & 15, i0 = qt * 64;

    const __nv_bfloat16* qh = g_qh + (size_t)beh * HD * SEQ;
    const __nv_bfloat16* ql = g_ql + (size_t)beh * HD * SEQ;
    const __nv_bfloat16* kh = g_kh + (size_t)beh * HD * SEQ;
    const __nv_bfloat16* kl = g_kl + (size_t)beh * HD * SEQ;

    // Stage Q tiles [64 d][64 s]
#pragma unroll
    for (int j = 0; j < 2; j++) {
        int f = t + j * 256;          // 0..511
        int d = f >> 3, cc = f & 7;
        cp16(sb + SQH + d * AQ_STRIDE + cc * 16, qh + (size_t)d * SEQ + i0 + cc * 8);
        cp16(sb + SQL + d * AQ_STRIDE + cc * 16, ql + (size_t)d * SEQ + i0 + cc * 8);
    }
    // Stage K chunk 0
#pragma unroll
    for (int j = 0; j < 8; j++) {
        int f = t + j * 256;          // 0..2047
        int d = f >> 5, cc = f & 31;
        cp16(sb + SKH + d * AK_STRIDE + cc * 16, kh + (size_t)d * SEQ + cc * 8);
        cp16(sb + SKL + d * AK_STRIDE + cc * 16, kl + (size_t)d * SEQ + cc * 8);
    }
    CP_COMMIT();

    const float SCALE = 0.125f;
    float rs[2][2] = {{0.f, 0.f}, {0.f, 0.f}};
    const int mat = lane >> 3, l7 = lane & 7;

    for (int c = 0; c < 4; c++) {
        CP_WAIT0();
        __syncthreads();

        float acc[2][8][4];
#pragma unroll
        for (int mi = 0; mi < 2; mi++)
#pragma unroll
            for (int ni = 0; ni < 8; ni++)
#pragma unroll
                for (int r = 0; r < 4; r++) acc[mi][ni][r] = 0.f;

#pragma unroll
        for (int ds = 0; ds < 4; ds++) {
            const int d0 = ds * 16;
            uint32_t ah[2][4], al[2][4], bh[4][4], bl[4][4];
            // A (trans): mats (m-lo,k-lo),(m-hi,k-lo),(m-lo,k-hi),(m-hi,k-hi)
            const int adrow = d0 + (mat >> 1) * 8 + l7;
#pragma unroll
            for (int mi = 0; mi < 2; mi++) {
                const int am = (wq * 32 + mi * 16 + (mat & 1) * 8) * 2;
                ldm_x4t(ah[mi], sb + SQH + adrow * AQ_STRIDE + am);
                ldm_x4t(al[mi], sb + SQL + adrow * AQ_STRIDE + am);
            }
            // B (trans): mats (n-lo,k-lo),(n-lo,k-hi),(n-hi,k-lo),(n-hi,k-hi)
            const int bdrow = d0 + (mat & 1) * 8 + l7;
#pragma unroll
            for (int np = 0; np < 4; np++) {
                const int bn = (wk * 64 + np * 16 + (mat >> 1) * 8) * 2;
                ldm_x4t(bh[np], sb + SKH + bdrow * AK_STRIDE + bn);
                ldm_x4t(bl[np], sb + SKL + bdrow * AK_STRIDE + bn);
            }
#pragma unroll
            for (int mi = 0; mi < 2; mi++)
#pragma unroll
                for (int ni = 0; ni < 8; ni++) {
                    const uint32_t* Bh = &bh[ni >> 1][(ni & 1) * 2];
                    const uint32_t* Bl = &bl[ni >> 1][(ni & 1) * 2];
                    mma_bf16(acc[mi][ni], ah[mi], Bh);
                    mma_bf16(acc[mi][ni], ah[mi], Bl);
                    mma_bf16(acc[mi][ni], al[mi], Bh);
                }
        }
        __syncthreads();   // all warps done reading K tiles

        if (c + 1 < 4) {   // overlap next K load with exp/P phase
            const int s0 = (c + 1) * 256;
#pragma unroll
            for (int j = 0; j < 8; j++) {
                int f = t + j * 256;
                int d = f >> 5, cc = f & 31;
                cp16(sb + SKH + d * AK_STRIDE + cc * 16, kh + (size_t)d * SEQ + s0 + cc * 8);
                cp16(sb + SKL + d * AK_STRIDE + cc * 16, kl + (size_t)d * SEQ + s0 + cc * 8);
            }
            CP_COMMIT();
        }

        // exp + P store + row-sum accumulate
        const int row0 = wq * 32 + (lane >> 2);
#pragma unroll
        for (int mi = 0; mi < 2; mi++) {
            const int row = row0 + mi * 16;
            float r0 = 0.f, r1 = 0.f;
#pragma unroll
            for (int ni = 0; ni < 8; ni++) {
                float p0 = __expf(acc[mi][ni][0] * SCALE);
                float p1 = __expf(acc[mi][ni][1] * SCALE);
                float p2 = __expf(acc[mi][ni][2] * SCALE);
                float p3 = __expf(acc[mi][ni][3] * SCALE);
                r0 += p0 + p1;  r1 += p2 + p3;
                const int col = c * 256 + wk * 64 + ni * 8 + (lane & 3) * 2;
                *(__nv_bfloat162*)(smc + SP + row * AP_STRIDE + col * 2) =
                    __floats2bfloat162_rn(p0, p1);
                *(__nv_bfloat162*)(smc + SP + (row + 8) * AP_STRIDE + col * 2) =
                    __floats2bfloat162_rn(p2, p3);
            }
            rs[mi][0] += r0;
            rs[mi][1] += r1;
        }
    }

    // Z: quad-reduce rs, deposit per-warp partials, combine
    float* red = (float*)(smc + SRED);
    float* rZ  = (float*)(smc + SRZ);
#pragma unroll
    for (int mi = 0; mi < 2; mi++)
#pragma unroll
        for (int hf = 0; hf < 2; hf++) {
            float v = rs[mi][hf];
            v += __shfl_xor_sync(0xFFFFFFFF, v, 1);
            v += __shfl_xor_sync(0xFFFFFFFF, v, 2);
            if ((lane & 3) == 0) {
                int row = wq * 32 + mi * 16 + (lane >> 2) + hf * 8;
                red[row * 4 + wk] = v;
            }
        }
    __syncthreads();
    if (t < 64) {
        float4 v = *(float4*)&red[t * 4];
        rZ[t] = 1.f / (v.x + v.y + v.z + v.w);
    }
    __syncthreads();

    // Pass 2: out[k] = sum_i P[i][k] * rZ[i]
    float s0 = 0.f, s1 = 0.f, s2 = 0.f, s3 = 0.f;
#pragma unroll 4
    for (int i = 0; i < 64; i++) {
        float r = rZ[i];
        __nv_bfloat162 w0 = *(__nv_bfloat162*)(smc + SP + i * AP_STRIDE + t * 4);
        __nv_bfloat162 w1 = *(__nv_bfloat162*)(smc + SP + i * AP_STRIDE + 1024 + t * 4);
        float2 f0 = __bfloat1622float2(w0);
        float2 f1 = __bfloat1622float2(w1);
        s0 += f0.x * r;  s1 += f0.y * r;
        s2 += f1.x * r;  s3 += f1.y * r;
    }
    float* gp = g_part + (size_t)bid * 1024;
    *(float2*)&gp[2 * t]       = make_float2(s0, s1);
    *(float2*)&gp[512 + 2 * t] = make_float2(s2, s3);
}

// ---------------------------------------------------------------------------
// Final reduce: out[b][k][e] = sum over h(4), qt(16)
// ---------------------------------------------------------------------------
__global__ __launch_bounds__(256)
void reduce_kernel(float* __restrict__ out)
{
    int tid = blockIdx.x * blockDim.x + threadIdx.x;
    if (tid >= BATCH * SEQ * NE) return;
    int e    = tid & 7;
    int kpos = (tid >> 3) & 1023;
    int b    = tid >> 13;
    float s = 0.f;
#pragma unroll
    for (int h = 0; h < NHEAD; h++) {
        int beh = b * 32 + e * 4 + h;
        const float* base = g_part + (size_t)(beh * 16) * 1024 + kpos;
#pragma unroll
        for (int qt = 0; qt < 16; qt++)
            s += base[qt * 1024];
    }
    out[tid] = s;
}

// ---------------------------------------------------------------------------
extern "C" void kernel_launch(void* const* d_in, const int* in_sizes, int n_in,
                              void* d_out, int out_size)
{
    const float* x  = (const float*)d_in[0];
    const float* Wq = (const float*)d_in[1];
    const float* bq = (const float*)d_in[2];
    const float* Wk = (const float*)d_in[3];
    const float* bk = (const float*)d_in[4];
    float* out = (float*)d_out;

    convert_x_kernel<<<(MROWS * DIN / 4) / 256, 256>>>(x);
    convert_wt_kernel<<<dim3(COUT / 32, DIN / 32, 2), 256>>>(Wq, Wk);

    cudaFuncSetAttribute(proj_mma_kernel, cudaFuncAttributeMaxDynamicSharedMemorySize, PROJ_SMEM);
    proj_mma_kernel<<<dim3(MROWS / 128, COUT / 128, 2), 256, PROJ_SMEM>>>(bq, bk);

    cudaFuncSetAttribute(attn_mma_kernel, cudaFuncAttributeMaxDynamicSharedMemorySize, ATTN_SMEM);
    attn_mma_kernel<<<2048, 256, ATTN_SMEM>>>();

    reduce_kernel<<<(BATCH * SEQ * NE + 255) / 256, 256>>>(out);
}

// round 6
// speedup vs baseline: 2.4378x; 1.0220x over previous
#include <cuda_runtime.h>
#include <cuda_bf16.h>
#include <cstdint>

#define BATCH 4
#define SEQ   1024
#define DIN   1024
#define HD    64
#define NE    8
#define NHEAD 4
#define COUT  (HD*NE*NHEAD)    // 2048
#define MROWS (BATCH*SEQ)      // 4096
#define NBEH  (BATCH*NE*NHEAD) // 128

// ---------------------------------------------------------------------------
// Scratch (no allocations allowed)
// ---------------------------------------------------------------------------
__device__ float g_part[(size_t)4096 * SEQ];            // per-block partials, 16 MB

__device__ __nv_bfloat16 g_xh[(size_t)MROWS * DIN];     // x hi
__device__ __nv_bfloat16 g_xl[(size_t)MROWS * DIN];     // x lo
__device__ __nv_bfloat16 g_wth[2][(size_t)COUT * DIN];  // W^T hi (q,k)
__device__ __nv_bfloat16 g_wtl[2][(size_t)COUT * DIN];  // W^T lo (q,k)

// q/k split bf16, layout [beh][d][s]
__device__ __nv_bfloat16 g_qh[(size_t)NBEH * HD * SEQ];
__device__ __nv_bfloat16 g_ql[(size_t)NBEH * HD * SEQ];
__device__ __nv_bfloat16 g_kh[(size_t)NBEH * HD * SEQ];
__device__ __nv_bfloat16 g_kl[(size_t)NBEH * HD * SEQ];

// ---------------------------------------------------------------------------
// sm_80+ primitives
// ---------------------------------------------------------------------------
__device__ __forceinline__ uint32_t smem_u32(const void* p) {
    uint32_t a;
    asm("{ .reg .u64 t; cvta.to.shared.u64 t, %1; cvt.u32.u64 %0, t; }" : "=r"(a) : "l"(p));
    return a;
}
__device__ __forceinline__ void ldm_x4(uint32_t* r, uint32_t addr) {
    asm volatile("ldmatrix.sync.aligned.m8n8.x4.shared.b16 {%0,%1,%2,%3}, [%4];"
        : "=r"(r[0]), "=r"(r[1]), "=r"(r[2]), "=r"(r[3]) : "r"(addr));
}
__device__ __forceinline__ void ldm_x4t(uint32_t* r, uint32_t addr) {
    asm volatile("ldmatrix.sync.aligned.m8n8.x4.trans.shared.b16 {%0,%1,%2,%3}, [%4];"
        : "=r"(r[0]), "=r"(r[1]), "=r"(r[2]), "=r"(r[3]) : "r"(addr));
}
__device__ __forceinline__ void mma_bf16(float* d, const uint32_t* a, const uint32_t* b) {
    asm volatile("mma.sync.aligned.m16n8k16.row.col.f32.bf16.bf16.f32 "
        "{%0,%1,%2,%3}, {%4,%5,%6,%7}, {%8,%9}, {%0,%1,%2,%3};"
        : "+f"(d[0]), "+f"(d[1]), "+f"(d[2]), "+f"(d[3])
        : "r"(a[0]), "r"(a[1]), "r"(a[2]), "r"(a[3]), "r"(b[0]), "r"(b[1]));
}
__device__ __forceinline__ void cp16(uint32_t dst, const void* src) {
    asm volatile("cp.async.cg.shared.global [%0], [%1], 16;" :: "r"(dst), "l"(src));
}
__device__ __forceinline__ float ex2(float x) {
    float y; asm("ex2.approx.ftz.f32 %0, %1;" : "=f"(y) : "f"(x)); return y;
}
#define CP_COMMIT() asm volatile("cp.async.commit_group;" ::: "memory")
#define CP_WAIT1()  asm volatile("cp.async.wait_group 1;" ::: "memory")
#define CP_WAIT0()  asm volatile("cp.async.wait_group 0;" ::: "memory")

// ---------------------------------------------------------------------------
// Split-convert x
// ---------------------------------------------------------------------------
__global__ __launch_bounds__(256)
void convert_x_kernel(const float* __restrict__ x)
{
    int i = blockIdx.x * 256 + threadIdx.x;
    float4 v = ((const float4*)x)[i];
    __nv_bfloat16 hx = __float2bfloat16(v.x), hy = __float2bfloat16(v.y);
    __nv_bfloat16 hz = __float2bfloat16(v.z), hw = __float2bfloat16(v.w);
    __nv_bfloat162* ph = (__nv_bfloat162*)g_xh;
    __nv_bfloat162* pl = (__nv_bfloat162*)g_xl;
    ph[i * 2 + 0] = __nv_bfloat162(hx, hy);
    ph[i * 2 + 1] = __nv_bfloat162(hz, hw);
    pl[i * 2 + 0] = __nv_bfloat162(__float2bfloat16(v.x - __bfloat162float(hx)),
                                   __float2bfloat16(v.y - __bfloat162float(hy)));
    pl[i * 2 + 1] = __nv_bfloat162(__float2bfloat16(v.z - __bfloat162float(hz)),
                                   __float2bfloat16(v.w - __bfloat162float(hw)));
}

// ---------------------------------------------------------------------------
// Split-convert + transpose W
// ---------------------------------------------------------------------------
__global__ __launch_bounds__(256)
void convert_wt_kernel(const float* __restrict__ Wq, const float* __restrict__ Wk)
{
    __shared__ float sm[32][33];
    const float* W = blockIdx.z ? Wk : Wq;
    __nv_bfloat16* oh = g_wth[blockIdx.z];
    __nv_bfloat16* ol = g_wtl[blockIdx.z];
    int n0 = blockIdx.x * 32, k0 = blockIdx.y * 32;
    int tx = threadIdx.x & 31, ty = threadIdx.x >> 5;
#pragma unroll
    for (int j = 0; j < 4; j++)
        sm[ty + j * 8][tx] = W[(size_t)(k0 + ty + j * 8) * COUT + n0 + tx];
    __syncthreads();
#pragma unroll
    for (int j = 0; j < 4; j++) {
        int row = ty + j * 8;
        float v = sm[tx][row];
        __nv_bfloat16 h = __float2bfloat16(v);
        size_t o = (size_t)(n0 + row) * DIN + k0 + tx;
        oh[o] = h;
        ol[o] = __float2bfloat16(v - __bfloat162float(h));
    }
}

// ---------------------------------------------------------------------------
// mma.sync projection GEMM; epilogue emits split bf16 q/k in [beh][d][s]
// ---------------------------------------------------------------------------
#define SROWB   80
#define TILE_B  (128 * SROWB)
#define STAGE_B (4 * TILE_B)
#define PROJ_SMEM (2 * STAGE_B)

__device__ __forceinline__ void split_store(__nv_bfloat16* ph, __nv_bfloat16* pl,
                                            size_t o, float v)
{
    __nv_bfloat16 h = __float2bfloat16(v);
    ph[o] = h;
    pl[o] = __float2bfloat16(v - __bfloat162float(h));
}

__device__ __forceinline__ void proj_prefetch(
    uint32_t sb, int stage, int k0, int t,
    const __nv_bfloat16* a_h, const __nv_bfloat16* a_l,
    const __nv_bfloat16* b_h, const __nv_bfloat16* b_l)
{
    const __nv_bfloat16* srcs[4] = { a_h, a_l, b_h, b_l };
    uint32_t st = sb + stage * STAGE_B;
#pragma unroll
    for (int tile = 0; tile < 4; tile++) {
#pragma unroll
        for (int j = 0; j < 2; j++) {
            int idx = t + j * 256;
            int row = idx >> 2, cc = idx & 3;
            cp16(st + tile * TILE_B + row * SROWB + cc * 16,
                 srcs[tile] + (size_t)row * DIN + k0 + cc * 8);
        }
    }
    CP_COMMIT();
}

__global__ void __launch_bounds__(256, 2)
proj_mma_kernel(const float* __restrict__ bq, const float* __restrict__ bk)
{
    extern __shared__ char smc[];
    const uint32_t sb = smem_u32(smc);
    const int t = threadIdx.x, wid = t >> 5, lane = t & 31;
    const int m0 = blockIdx.x * 128, n0 = blockIdx.y * 128, z = blockIdx.z;
    const int wm = (wid & 3) * 32, wn = (wid >> 2) * 64;

    const __nv_bfloat16* a_h = g_xh + (size_t)m0 * DIN;
    const __nv_bfloat16* a_l = g_xl + (size_t)m0 * DIN;
    const __nv_bfloat16* b_h = g_wth[z] + (size_t)n0 * DIN;
    const __nv_bfloat16* b_l = g_wtl[z] + (size_t)n0 * DIN;
    const float* bias = z ? bk : bq;
    __nv_bfloat16* oh = z ? g_kh : g_qh;
    __nv_bfloat16* ol = z ? g_kl : g_ql;

    float acc[2][8][4];
#pragma unroll
    for (int mi = 0; mi < 2; mi++)
#pragma unroll
        for (int ni = 0; ni < 8; ni++)
#pragma unroll
            for (int r = 0; r < 4; r++) acc[mi][ni][r] = 0.f;

    proj_prefetch(sb, 0, 0, t, a_h, a_l, b_h, b_l);

    const int NCHUNK = DIN / 32;
    for (int c = 0; c < NCHUNK; ++c) {
        if (c + 1 < NCHUNK) {
            proj_prefetch(sb, (c + 1) & 1, (c + 1) * 32, t, a_h, a_l, b_h, b_l);
            CP_WAIT1();
        } else {
            CP_WAIT0();
        }
        __syncthreads();

        const uint32_t st  = sb + (c & 1) * STAGE_B;
        const uint32_t sAh = st, sAl = st + TILE_B;
        const uint32_t sBh = st + 2 * TILE_B, sBl = st + 3 * TILE_B;

#pragma unroll
        for (int kk = 0; kk < 32; kk += 16) {
            uint32_t ah[2][4], al[2][4];
            const int arow = wm + (lane & 15);
            const int acol = kk + (lane >> 4) * 8;
#pragma unroll
            for (int mi = 0; mi < 2; mi++) {
                ldm_x4(ah[mi], sAh + (arow + mi * 16) * SROWB + acol * 2);
                ldm_x4(al[mi], sAl + (arow + mi * 16) * SROWB + acol * 2);
            }
            const int g = lane >> 3;
            const int brow_off = (g >> 1) * 8 + (lane & 7);
            const int bcol = kk + (g & 1) * 8;
#pragma unroll
            for (int np = 0; np < 4; np++) {     // B loaded per-pair: lower live regs
                uint32_t bh[4], bl[4];
                int brow = wn + np * 16 + brow_off;
                ldm_x4(bh, sBh + brow * SROWB + bcol * 2);
                ldm_x4(bl, sBl + brow * SROWB + bcol * 2);
#pragma unroll
                for (int mi = 0; mi < 2; mi++)
#pragma unroll
                    for (int nq = 0; nq < 2; nq++) {
                        float* A = acc[mi][np * 2 + nq];
                        mma_bf16(A, ah[mi], &bh[nq * 2]);
                        mma_bf16(A, ah[mi], &bl[nq * 2]);
                        mma_bf16(A, al[mi], &bh[nq * 2]);
                    }
            }
        }
        __syncthreads();
    }

    // Epilogue: bias + split-bf16 store to [beh][d][s]
#pragma unroll
    for (int mi = 0; mi < 2; mi++) {
        int r = wm + mi * 16 + (lane >> 2);
        int m = m0 + r;
        int b = m >> 10, s = m & 1023;
#pragma unroll
        for (int ni = 0; ni < 8; ni++) {
            int col = n0 + wn + ni * 8 + (lane & 3) * 2;
            float bv0 = __ldg(&bias[col]);
            float bv1 = __ldg(&bias[col + 1]);
            int d = col >> 5, e0 = col & 31;
            size_t o0 = ((size_t)(b * 32 + e0) * HD + d) * SEQ + s;
            size_t o1 = ((size_t)(b * 32 + e0 + 1) * HD + d) * SEQ + s;
            split_store(oh, ol, o0,     acc[mi][ni][0] + bv0);
            split_store(oh, ol, o1,     acc[mi][ni][1] + bv1);
            split_store(oh, ol, o0 + 8, acc[mi][ni][2] + bv0);
            split_store(oh, ol, o1 + 8, acc[mi][ni][3] + bv1);
        }
    }
}

// ---------------------------------------------------------------------------
// MMA attention v2: block = (beh, 32-query tile), 4096 blocks, 2 CTAs/SM.
// K chunks of 64, double-buffered cp.async (prefetch overlaps MMA).
// 8 warps as 2q x 4k; warp tile 16x16 per chunk.
// ---------------------------------------------------------------------------
#define AQ_STR 80                     // 32 q * 2B + 16 pad
#define AK_STR 144                    // 64 k * 2B + 16 pad
#define AP_STR 2064                   // 1024 k * 2B + 16 pad
#define KBUF_B 18432                  // per buffer: hi (9216) + lo (9216)
#define SQH 0
#define SQL 5120
#define SKB 10240                     // 2 buffers -> +36864
#define SP  47104                     // 32 * 2064 = 66048
#define SRED 113152                   // 32 rows x 4 warps x 4B = 512
#define SRZ  113664                   // 32 x 4B
#define ATTN_SMEM 113792

__device__ __forceinline__ void attn_prefetch_k(
    uint32_t sb, int buf, int ck, int t,
    const __nv_bfloat16* kh, const __nv_bfloat16* kl)
{
    uint32_t base = sb + SKB + buf * KBUF_B;
#pragma unroll
    for (int j = 0; j < 2; j++) {
        int f = t + j * 256;          // 0..511
        int d = f >> 3, cc = f & 7;
        cp16(base + d * AK_STR + cc * 16,        kh + (size_t)d * SEQ + ck + cc * 8);
        cp16(base + 9216 + d * AK_STR + cc * 16, kl + (size_t)d * SEQ + ck + cc * 8);
    }
    CP_COMMIT();
}

__global__ void __launch_bounds__(256, 2) attn_mma_kernel()
{
    extern __shared__ char smc[];
    const uint32_t sb = smem_u32(smc);
    const int t = threadIdx.x, wid = t >> 5, lane = t & 31;
    const int wq = wid >> 2, wk = wid & 3;
    const int bid = blockIdx.x, beh = bid >> 5, qt = bid & 31, i0 = qt * 32;

    const __nv_bfloat16* qh = g_qh + (size_t)beh * HD * SEQ;
    const __nv_bfloat16* ql = g_ql + (size_t)beh * HD * SEQ;
    const __nv_bfloat16* kh = g_kh + (size_t)beh * HD * SEQ;
    const __nv_bfloat16* kl = g_kl + (size_t)beh * HD * SEQ;

    // Stage Q [64 d][32 q] hi/lo (uncommitted; joins K0's group)
    {
        int d = t >> 2, cc = t & 3;
        cp16(sb + SQH + d * AQ_STR + cc * 16, qh + (size_t)d * SEQ + i0 + cc * 8);
        cp16(sb + SQL + d * AQ_STR + cc * 16, ql + (size_t)d * SEQ + i0 + cc * 8);
    }
    attn_prefetch_k(sb, 0, 0, t, kh, kl);

    const float C = 0.18033688f;      // 0.125 * log2(e)
    const int mat = lane >> 3, l7 = lane & 7;
    float rs0 = 0.f, rs1 = 0.f;

    for (int c = 0; c < 16; c++) {
        if (c < 15) { attn_prefetch_k(sb, (c + 1) & 1, (c + 1) * 64, t, kh, kl); CP_WAIT1(); }
        else        { CP_WAIT0(); }
        __syncthreads();

        float acc[2][4];
#pragma unroll
        for (int ni = 0; ni < 2; ni++)
#pragma unroll
            for (int r = 0; r < 4; r++) acc[ni][r] = 0.f;

        const uint32_t kb = sb + SKB + (c & 1) * KBUF_B;
#pragma unroll
        for (int ds = 0; ds < 4; ds++) {
            const int d0 = ds * 16;
            uint32_t ah[4], al[4], bh[4], bl[4];
            const int adrow = d0 + (mat >> 1) * 8 + l7;
            const int am = (wq * 16 + (mat & 1) * 8) * 2;
            ldm_x4t(ah, sb + SQH + adrow * AQ_STR + am);
            ldm_x4t(al, sb + SQL + adrow * AQ_STR + am);
            const int bdrow = d0 + (mat & 1) * 8 + l7;
            const int bn = (wk * 16 + (mat >> 1) * 8) * 2;
            ldm_x4t(bh, kb + bdrow * AK_STR + bn);
            ldm_x4t(bl, kb + 9216 + bdrow * AK_STR + bn);
#pragma unroll
            for (int ni = 0; ni < 2; ni++) {
                mma_bf16(acc[ni], ah, &bh[ni * 2]);
                mma_bf16(acc[ni], ah, &bl[ni * 2]);
                mma_bf16(acc[ni], al, &bh[ni * 2]);
            }
        }
        __syncthreads();

        // exp -> P (bf16 smem) + row-sum accumulate
        const int row = wq * 16 + (lane >> 2);
#pragma unroll
        for (int ni = 0; ni < 2; ni++) {
            float p0 = ex2(acc[ni][0] * C);
            float p1 = ex2(acc[ni][1] * C);
            float p2 = ex2(acc[ni][2] * C);
            float p3 = ex2(acc[ni][3] * C);
            rs0 += p0 + p1;
            rs1 += p2 + p3;
            const int col = c * 64 + wk * 16 + ni * 8 + (lane & 3) * 2;
            *(__nv_bfloat162*)(smc + SP + row * AP_STR + col * 2) =
                __floats2bfloat162_rn(p0, p1);
            *(__nv_bfloat162*)(smc + SP + (row + 8) * AP_STR + col * 2) =
                __floats2bfloat162_rn(p2, p3);
        }
    }

    // Z: quad-reduce, per-warp deposit, combine
    float* red = (float*)(smc + SRED);
    float* rZ  = (float*)(smc + SRZ);
    rs0 += __shfl_xor_sync(0xFFFFFFFF, rs0, 1);
    rs0 += __shfl_xor_sync(0xFFFFFFFF, rs0, 2);
    rs1 += __shfl_xor_sync(0xFFFFFFFF, rs1, 1);
    rs1 += __shfl_xor_sync(0xFFFFFFFF, rs1, 2);
    if ((lane & 3) == 0) {
        int row = wq * 16 + (lane >> 2);
        red[row * 4 + wk]       = rs0;
        red[(row + 8) * 4 + wk] = rs1;
    }
    __syncthreads();
    if (t < 32) {
        float4 v = *(float4*)&red[t * 4];
        rZ[t] = 1.f / (v.x + v.y + v.z + v.w);
    }
    __syncthreads();

    // Pass 2: out[k] = sum_i P[i][k] * rZ[i]; thread owns 4 consecutive k
    float s0 = 0.f, s1 = 0.f, s2 = 0.f, s3 = 0.f;
#pragma unroll 8
    for (int i = 0; i < 32; i++) {
        float r = rZ[i];
        __nv_bfloat162 w0 = *(__nv_bfloat162*)(smc + SP + i * AP_STR + t * 8);
        __nv_bfloat162 w1 = *(__nv_bfloat162*)(smc + SP + i * AP_STR + t * 8 + 4);
        float2 f0 = __bfloat1622float2(w0);
        float2 f1 = __bfloat1622float2(w1);
        s0 += f0.x * r;  s1 += f0.y * r;
        s2 += f1.x * r;  s3 += f1.y * r;
    }
    float* gp = g_part + (size_t)bid * 1024;
    *(float4*)&gp[t * 4] = make_float4(s0, s1, s2, s3);
}

// ---------------------------------------------------------------------------
// Final reduce: out[b][k][e] = sum over h(4), qt(32)
// ---------------------------------------------------------------------------
__global__ __launch_bounds__(256)
void reduce_kernel(float* __restrict__ out)
{
    int tid = blockIdx.x * blockDim.x + threadIdx.x;
    if (tid >= BATCH * SEQ * NE) return;
    int e    = tid & 7;
    int kpos = (tid >> 3) & 1023;
    int b    = tid >> 13;
    float s = 0.f;
#pragma unroll
    for (int h = 0; h < NHEAD; h++) {
        int beh = b * 32 + e * 4 + h;
        const float* base = g_part + (size_t)(beh * 32) * 1024 + kpos;
#pragma unroll
        for (int qt = 0; qt < 32; qt++)
            s += base[qt * 1024];
    }
    out[tid] = s;
}

// ---------------------------------------------------------------------------
extern "C" void kernel_launch(void* const* d_in, const int* in_sizes, int n_in,
                              void* d_out, int out_size)
{
    const float* x  = (const float*)d_in[0];
    const float* Wq = (const float*)d_in[1];
    const float* bq = (const float*)d_in[2];
    const float* Wk = (const float*)d_in[3];
    const float* bk = (const float*)d_in[4];
    float* out = (float*)d_out;

    convert_x_kernel<<<(MROWS * DIN / 4) / 256, 256>>>(x);
    convert_wt_kernel<<<dim3(COUT / 32, DIN / 32, 2), 256>>>(Wq, Wk);

    cudaFuncSetAttribute(proj_mma_kernel, cudaFuncAttributeMaxDynamicSharedMemorySize, PROJ_SMEM);
    proj_mma_kernel<<<dim3(MROWS / 128, COUT / 128, 2), 256, PROJ_SMEM>>>(bq, bk);

    cudaFuncSetAttribute(attn_mma_kernel, cudaFuncAttributeMaxDynamicSharedMemorySize, ATTN_SMEM);
    attn_mma_kernel<<<4096, 256, ATTN_SMEM>>>();

    reduce_kernel<<<(BATCH * SEQ * NE + 255) / 256, 256>>>(out);
}